// round 4
// baseline (speedup 1.0000x reference)
#include <cuda_runtime.h>
#include <cuda_bf16.h>
#include <cstdint>

#define NB 64
#define NT 512
#define NI 128
#define NH 256
#define NR 20
#define NDA 50
#define NC 10
#define G4 1024

// ----------------------------- device scratch ------------------------------
__device__ float g_S   [NB * NR * NT];              // [b][r][t]
__device__ float g_E   [NB * NT * NR];              // [b][t][r]
__device__ float g_Dinv[NB * NT * NR];              // [b][t][r]
__device__ float g_M   [(size_t)NB * NT * NI];      // [b][t][i]
__device__ float g_GXT [(size_t)NT * G4 * NB];      // [t][g][b]
__device__ float g_h   [2][NH * 64];                // [buf][hd*64 + b]
__device__ unsigned g_bar;

__device__ __forceinline__ void ffma2(unsigned long long& acc,
                                      unsigned long long a,
                                      unsigned long long b) {
    asm("fma.rn.f32x2 %0, %1, %2, %0;" : "+l"(acc) : "l"(a), "l"(b));
}
__device__ __forceinline__ float sigf(float v) {
    return __fdividef(1.0f, 1.0f + __expf(-v));
}
__device__ __forceinline__ float tanhfast(float v) {
    float ax = fabsf(v);
    float e = __expf(-2.0f * ax);
    float t = __fdividef(1.0f - e, 1.0f + e);
    return copysignf(t, v);
}

// ------------------------------ K1: scores (+init) --------------------------
__global__ void k_scores(const float* __restrict__ x,
                         const float* __restrict__ W1, const float* __restrict__ b1,
                         const float* __restrict__ W2, const float* __restrict__ b2) {
    __shared__ float W1s[NDA][NI + 1];
    __shared__ float W2s[NR][NDA + 1];
    __shared__ float b1s[NDA];
    __shared__ float b2s[NR];
    __shared__ float xr[8][NI];
    __shared__ float ssm[8][NDA + 1];
    int tid = threadIdx.x;

    if (blockIdx.x == 0) {           // fused init
        for (int j = tid; j < NH * 64; j += 256) g_h[0][j] = 1.0f;
        if (tid == 0) g_bar = 0u;
    }

    for (int idx = tid; idx < NDA * NI; idx += 256) W1s[idx / NI][idx % NI] = W1[idx];
    for (int idx = tid; idx < NR * NDA; idx += 256) W2s[idx / NDA][idx % NDA] = W2[idx];
    if (tid < NDA) b1s[tid] = b1[tid];
    if (tid < NR)  b2s[tid] = b2[tid];
    __syncthreads();

    int w = tid >> 5, lane = tid & 31;
    int bt = blockIdx.x * 8 + w;
    const float* xp = x + (size_t)bt * NI;
    for (int i = lane; i < NI; i += 32) xr[w][i] = xp[i];
    __syncwarp();
    for (int d = lane; d < NDA; d += 32) {
        float acc = b1s[d];
        #pragma unroll 16
        for (int i = 0; i < NI; i++) acc = fmaf(xr[w][i], W1s[d][i], acc);
        ssm[w][d] = tanhf(acc);
    }
    __syncwarp();
    if (lane < NR) {
        float acc = b2s[lane];
        #pragma unroll
        for (int d = 0; d < NDA; d++) acc = fmaf(ssm[w][d], W2s[lane][d], acc);
        int b = bt >> 9, t = bt & 511;
        g_S[((size_t)b * NR + lane) * NT + t] = acc;
    }
}

// --------------- K2: max over t, exp, prefix-sum denominators ---------------
// block = (b, r); 128 threads; thread owns t = 4*tid..4*tid+3 (contiguous)
__global__ void k_maxexpdinv() {
    int br = blockIdx.x;
    int b = br / NR, r = br % NR;
    int tid = threadIdx.x;
    int w = tid >> 5, lane = tid & 31;
    const float* Sp = g_S + (size_t)br * NT;
    float4 v = *(const float4*)(Sp + 4 * tid);

    __shared__ float red[4];
    __shared__ float wsum[4];
    float m = fmaxf(fmaxf(v.x, v.y), fmaxf(v.z, v.w));
    for (int o = 16; o; o >>= 1) m = fmaxf(m, __shfl_xor_sync(~0u, m, o));
    if (lane == 0) red[w] = m;
    __syncthreads();
    m = fmaxf(fmaxf(red[0], red[1]), fmaxf(red[2], red[3]));

    float e0 = __expf(v.x - m), e1 = __expf(v.y - m);
    float e2 = __expf(v.z - m), e3 = __expf(v.w - m);
    float ls = e0 + e1 + e2 + e3;

    // warp inclusive scan of per-thread sums
    float s = ls;
    for (int o = 1; o < 32; o <<= 1) {
        float n = __shfl_up_sync(~0u, s, o);
        if (lane >= o) s += n;
    }
    if (lane == 31) wsum[w] = s;
    __syncthreads();
    float base = 0.0f;
    #pragma unroll
    for (int ww = 0; ww < 4; ww++) if (ww < w) base += wsum[ww];

    float excl = base + s - ls;          // exclusive prefix at this thread's t0
    float d0 = excl + e0;
    float d1 = d0 + e1;
    float d2 = d1 + e2;
    float d3 = d2 + e3;

    int t0 = 4 * tid;
    size_t a0 = ((size_t)b * NT + t0) * NR + r;
    g_E[a0]            = e0;
    g_E[a0 + NR]       = e1;
    g_E[a0 + 2 * NR]   = e2;
    g_E[a0 + 3 * NR]   = e3;
    g_Dinv[a0]          = __fdividef(1.0f, d0);
    g_Dinv[a0 + NR]     = __fdividef(1.0f, d1);
    g_Dinv[a0 + 2 * NR] = __fdividef(1.0f, d2);
    g_Dinv[a0 + 3 * NR] = __fdividef(1.0f, d3);
}

// --------------------- K3: M via per-chunk recompute (no syncs) -------------
// block = (b, chunk of 64 t); 128 threads (i). Phase1 rebuilds N up to chunk start.
__global__ void k_attnM(const float* __restrict__ x) {
    int bc = blockIdx.x;
    int b = bc >> 3, c = bc & 7;
    int i = threadIdx.x;
    float N[NR];
    #pragma unroll
    for (int r = 0; r < NR; r++) N[r] = 0.0f;

    const float* xb = x + ((size_t)b * NT) * NI + i;
    const float* Eb = g_E + ((size_t)b * NT) * NR;
    const float* Db = g_Dinv + ((size_t)b * NT) * NR;
    float* Mb = g_M + ((size_t)b * NT) * NI + i;

    int tstart = c * 64;
    for (int t = 0; t < tstart; t++) {
        float xv = xb[(size_t)t * NI];
        #pragma unroll
        for (int r = 0; r < NR; r++)
            N[r] = fmaf(Eb[(size_t)t * NR + r], xv, N[r]);
    }
    for (int tl = 0; tl < 64; tl++) {
        int t = tstart + tl;
        float xv = xb[(size_t)t * NI];
        float acc = 0.0f;
        #pragma unroll
        for (int r = 0; r < NR; r++) {
            N[r] = fmaf(Eb[(size_t)t * NR + r], xv, N[r]);
            acc = fmaf(N[r], Db[(size_t)t * NR + r], acc);
        }
        Mb[(size_t)t * NI] = acc * 0.05f;
    }
}

// --------------- K4: gx GEMM (f32x2) writing GXT[t][g][b] directly ----------
// tile: 64 b (rows, fixed t) x 64 g; K=128 in 2 chunks. blockIdx = (t, n-tile)
#define GEMM_SMEM ((64 * 130 + 64 * 64) * 4)
__global__ void __launch_bounds__(256) k_gemm(const float* __restrict__ Wih,
                                              const float* __restrict__ bias) {
    extern __shared__ float smg[];
    float* As2 = smg;             // [64 k][130] (pair-duplicated, stride 130)
    float* Bs  = smg + 64 * 130;  // [64 k][64 n]
    int tid = threadIdx.x;
    int t0 = blockIdx.x;
    int n0 = blockIdx.y * 64;
    int tn = tid & 15, tm = tid >> 4;

    unsigned long long acc[4][2] = {};
    for (int kc = 0; kc < 2; kc++) {
        #pragma unroll
        for (int pass = 0; pass < 4; pass++) {
            int idx = tid + pass * 256;
            int row = idx >> 4, c4 = idx & 15;
            float4 va = *(const float4*)&g_M[((size_t)row * NT + t0) * NI + kc * 64 + c4 * 4];
            *(float2*)&As2[(c4 * 4 + 0) * 130 + 2 * row] = make_float2(va.x, va.x);
            *(float2*)&As2[(c4 * 4 + 1) * 130 + 2 * row] = make_float2(va.y, va.y);
            *(float2*)&As2[(c4 * 4 + 2) * 130 + 2 * row] = make_float2(va.z, va.z);
            *(float2*)&As2[(c4 * 4 + 3) * 130 + 2 * row] = make_float2(va.w, va.w);
            float4 vb = *(const float4*)&Wih[(size_t)(kc * 64 + row) * G4 + n0 + c4 * 4];
            *(float4*)&Bs[row * 64 + c4 * 4] = vb;
        }
        __syncthreads();
        #pragma unroll 8
        for (int kk = 0; kk < 64; kk++) {
            ulonglong2 bv = *(const ulonglong2*)&Bs[kk * 64 + tn * 4];
            #pragma unroll
            for (int j = 0; j < 4; j++) {
                unsigned long long av =
                    *(const unsigned long long*)&As2[kk * 130 + 2 * (tm * 4 + j)];
                ffma2(acc[j][0], av, bv.x);
                ffma2(acc[j][1], av, bv.y);
            }
        }
        __syncthreads();
    }
    float4 bb = *(const float4*)&bias[n0 + tn * 4];
    float bbv[4] = {bb.x, bb.y, bb.z, bb.w};
    #pragma unroll
    for (int nn = 0; nn < 4; nn++) {
        float4 o;
        float2 f0 = *(float2*)&acc[0][nn >> 1];
        float2 f1 = *(float2*)&acc[1][nn >> 1];
        float2 f2 = *(float2*)&acc[2][nn >> 1];
        float2 f3 = *(float2*)&acc[3][nn >> 1];
        if (nn & 1) { o.x = f0.y; o.y = f1.y; o.z = f2.y; o.w = f3.y; }
        else        { o.x = f0.x; o.y = f1.x; o.z = f2.x; o.w = f3.x; }
        o.x += bbv[nn]; o.y += bbv[nn]; o.z += bbv[nn]; o.w += bbv[nn];
        *(float4*)&g_GXT[((size_t)t0 * G4 + n0 + tn * 4 + nn) * 64 + tm * 4] = o;
    }
}

// ------------------------------ K5: LSTM recurrence -------------------------
#define LSTM_SMEM ((NH * 64 + NH * 16 + 4 * 8 * 64 + 128) * 4)

__global__ void __launch_bounds__(256, 1) k_lstm(const float* __restrict__ Whh) {
    extern __shared__ float sm[];
    float* hs   = sm;
    float* Ws2  = hs + NH * 64;
    float* gred = Ws2 + NH * 16;
    float* csm  = gred + 4 * 8 * 64;

    int bk = blockIdx.x;
    int tid = threadIdx.x;
    int p = tid & 15, q = (tid >> 4) & 3, u = tid >> 6;

    for (int idx = tid; idx < NH * 8; idx += 256) {
        int k = idx >> 3, c = idx & 7;
        float w = Whh[(size_t)k * G4 + (c & 3) * NH + 2 * bk + (c >> 2)];
        Ws2[idx * 2] = w;
        Ws2[idx * 2 + 1] = w;
    }
    if (tid < 128) csm[tid] = 1.0f;
    __syncthreads();

    int bbg = tid & 63, hig = (tid >> 6) & 1;

    // prefetch gx for t=0
    float pg[4];
    if (tid < 128) {
        const float* gp = g_GXT + ((size_t)0 * G4 + 2 * bk + hig) * 64 + bbg;
        #pragma unroll
        for (int g = 0; g < 4; g++) pg[g] = __ldcs(gp + (size_t)g * NH * 64);
    }

    for (int t = 0; t < NT; t++) {
        const float* hin = g_h[t & 1];
        float* hout = g_h[(t + 1) & 1];

        float4 r1[8];
        #pragma unroll
        for (int j = 0; j < 8; j++)
            r1[j] = __ldcg((const float4*)(hin + tid * 4 + j * 1024));
        #pragma unroll
        for (int j = 0; j < 8; j++)
            *(float4*)(hs + tid * 4 + j * 1024) = r1[j];
        __syncthreads();

        float4 r2[8];
        #pragma unroll
        for (int j = 0; j < 8; j++)
            r2[j] = __ldcg((const float4*)(hin + 8192 + tid * 4 + j * 1024));

        unsigned long long a0 = 0ull, a1 = 0ull, a2 = 0ull, a3 = 0ull;
        {
            const float* hp = hs + (u * 32) * 64 + 4 * p;
            const float* wp = Ws2 + (u * 32) * 16 + 4 * q;
            #pragma unroll
            for (int k = 0; k < 32; k++) {
                ulonglong2 hv = *(const ulonglong2*)hp;
                ulonglong2 wv = *(const ulonglong2*)wp;
                ffma2(a0, hv.x, wv.x);
                ffma2(a1, hv.y, wv.x);
                ffma2(a2, hv.x, wv.y);
                ffma2(a3, hv.y, wv.y);
                hp += 64; wp += 16;
            }
        }
        #pragma unroll
        for (int j = 0; j < 8; j++)
            *(float4*)(hs + 8192 + tid * 4 + j * 1024) = r2[j];
        __syncthreads();
        {
            const float* hp = hs + (128 + u * 32) * 64 + 4 * p;
            const float* wp = Ws2 + (128 + u * 32) * 16 + 4 * q;
            #pragma unroll
            for (int k = 0; k < 32; k++) {
                ulonglong2 hv = *(const ulonglong2*)hp;
                ulonglong2 wv = *(const ulonglong2*)wp;
                ffma2(a0, hv.x, wv.x);
                ffma2(a1, hv.y, wv.x);
                ffma2(a2, hv.x, wv.y);
                ffma2(a3, hv.y, wv.y);
                hp += 64; wp += 16;
            }
        }
        {
            float* gr = gred + ((u * 8 + 2 * q) * 64 + 4 * p);
            ulonglong2 v01; v01.x = a0; v01.y = a1;
            ulonglong2 v23; v23.x = a2; v23.y = a3;
            *(ulonglong2*)gr = v01;
            *(ulonglong2*)(gr + 64) = v23;
        }
        __syncthreads();

        float pgn[4];
        if (tid < 128) {
            // prefetch gx for t+1 (hidden behind gates + barrier)
            int tn = (t + 1) & (NT - 1);
            const float* gp = g_GXT + ((size_t)tn * G4 + 2 * bk + hig) * 64 + bbg;
            #pragma unroll
            for (int g = 0; g < 4; g++) pgn[g] = __ldcs(gp + (size_t)g * NH * 64);

            float gv[4];
            #pragma unroll
            for (int g = 0; g < 4; g++) {
                int c = hig * 4 + g;
                float s = gred[(0 * 8 + c) * 64 + bbg] + gred[(1 * 8 + c) * 64 + bbg]
                        + gred[(2 * 8 + c) * 64 + bbg] + gred[(3 * 8 + c) * 64 + bbg];
                gv[g] = s + pg[g];
            }
            float i_t = sigf(gv[0]);
            float f_t = sigf(gv[1]);
            float g_t = tanhfast(gv[2]);
            float o_t = sigf(gv[3]);
            float cc = f_t * csm[tid] + i_t * g_t;
            csm[tid] = cc;
            __stcg(&hout[(2 * bk + hig) * 64 + bbg], o_t * tanhfast(cc));
        }
        __threadfence();
        __syncthreads();
        if (tid == 0) atomicAdd(&g_bar, 1u);
        // per-warp lane0 spin, parallel release
        unsigned target = 128u * (unsigned)(t + 1);
        if ((tid & 31) == 0) {
            while (*(volatile unsigned*)&g_bar < target) { }
        }
        __syncwarp();
        #pragma unroll
        for (int g = 0; g < 4; g++) pg[g] = pgn[g];
    }
}

// ------------------------------ K6: head + softmax --------------------------
__global__ void k_head(const float* __restrict__ Wfc, const float* __restrict__ bfc,
                       float* __restrict__ out) {
    int b = blockIdx.x;
    int lane = threadIdx.x;
    __shared__ float hsm[NH];
    for (int k = lane; k < NH; k += 32) hsm[k] = g_h[0][k * 64 + b];
    __syncwarp();
    float l = -1e30f;
    if (lane < NC) {
        float acc = bfc[lane];
        #pragma unroll 8
        for (int k = 0; k < NH; k++) acc = fmaf(hsm[k], Wfc[lane * NH + k], acc);
        l = acc;
    }
    float m = l;
    for (int o = 16; o; o >>= 1) m = fmaxf(m, __shfl_xor_sync(~0u, m, o));
    float e = (lane < NC) ? __expf(l - m) : 0.0f;
    float s = e;
    for (int o = 16; o; o >>= 1) s += __shfl_xor_sync(~0u, s, o);
    if (lane < NC) out[b * NC + lane] = e / s;
}

// ------------------------------ launch --------------------------------------
extern "C" void kernel_launch(void* const* d_in, const int* in_sizes, int n_in,
                              void* d_out, int out_size) {
    const float* x    = (const float*)d_in[0];
    const float* W_ih = (const float*)d_in[1];
    const float* W_hh = (const float*)d_in[2];
    const float* b    = (const float*)d_in[3];
    const float* W1   = (const float*)d_in[4];
    const float* b1   = (const float*)d_in[5];
    const float* W2   = (const float*)d_in[6];
    const float* b2   = (const float*)d_in[7];
    const float* Wfc  = (const float*)d_in[8];
    const float* bfc  = (const float*)d_in[9];
    float* out = (float*)d_out;

    cudaFuncSetAttribute(k_lstm, cudaFuncAttributeMaxDynamicSharedMemorySize, LSTM_SMEM);
    cudaFuncSetAttribute(k_gemm, cudaFuncAttributeMaxDynamicSharedMemorySize, GEMM_SMEM);

    k_scores<<<4096, 256>>>(x, W1, b1, W2, b2);            // idx 0 (+init)
    k_maxexpdinv<<<NB * NR, 128>>>();                      // idx 1
    k_attnM<<<NB * 8, 128>>>(x);                           // idx 2
    {
        dim3 grid(NT, 16);
        k_gemm<<<grid, 256, GEMM_SMEM>>>(W_ih, b);         // idx 3 (ncu target)
    }
    k_lstm<<<128, 256, LSTM_SMEM>>>(W_hh);                 // idx 4
    k_head<<<NB, 32>>>(Wfc, bfc, out);                     // idx 5
}

// round 6
// speedup vs baseline: 1.1163x; 1.1163x over previous
#include <cuda_runtime.h>
#include <cuda_bf16.h>
#include <cstdint>

#define NB 64
#define NT 512
#define NI 128
#define NH 256
#define NR 20
#define NDA 50
#define NC 10
#define G4 1024

// ----------------------------- device scratch ------------------------------
__device__ float g_S   [NB * NR * NT];              // [b][r][t]
__device__ float g_E   [NB * NT * NR];              // [b][t][r]
__device__ float g_Dinv[NB * NT * NR];              // [b][t][r]
__device__ float g_M   [(size_t)NB * NT * NI];      // [b][t][i]  (m = b*T+t)
__device__ float g_GX  [(size_t)NB * NT * G4];      // [m][g]
__device__ float g_GXT [(size_t)NT * G4 * NB];      // [t][g][b]
__device__ float g_h   [2][NH * 64];                // [buf][hd*64 + b]
__device__ unsigned g_bar;

__device__ __forceinline__ void ffma2(unsigned long long& acc,
                                      unsigned long long a,
                                      unsigned long long b) {
    asm("fma.rn.f32x2 %0, %1, %2, %0;" : "+l"(acc) : "l"(a), "l"(b));
}
__device__ __forceinline__ float sigf(float v) {
    return __fdividef(1.0f, 1.0f + __expf(-v));
}
__device__ __forceinline__ float tanhfast(float v) {
    float ax = fabsf(v);
    float e = __expf(-2.0f * ax);
    float t = __fdividef(1.0f - e, 1.0f + e);
    return copysignf(t, v);
}

// ------------------------------ K1: scores (+init) --------------------------
__global__ void k_scores(const float* __restrict__ x,
                         const float* __restrict__ W1, const float* __restrict__ b1,
                         const float* __restrict__ W2, const float* __restrict__ b2) {
    __shared__ float W1s[NDA][NI + 1];
    __shared__ float W2s[NR][NDA + 1];
    __shared__ float b1s[NDA];
    __shared__ float b2s[NR];
    __shared__ float xr[8][NI];
    __shared__ float ssm[8][NDA + 1];
    int tid = threadIdx.x;

    if (blockIdx.x == 0) {
        for (int j = tid; j < NH * 64; j += 256) g_h[0][j] = 1.0f;
        if (tid == 0) g_bar = 0u;
    }

    for (int idx = tid; idx < NDA * NI; idx += 256) W1s[idx / NI][idx % NI] = W1[idx];
    for (int idx = tid; idx < NR * NDA; idx += 256) W2s[idx / NDA][idx % NDA] = W2[idx];
    if (tid < NDA) b1s[tid] = b1[tid];
    if (tid < NR)  b2s[tid] = b2[tid];
    __syncthreads();

    int w = tid >> 5, lane = tid & 31;
    int bt = blockIdx.x * 8 + w;
    const float* xp = x + (size_t)bt * NI;
    for (int i = lane; i < NI; i += 32) xr[w][i] = xp[i];
    __syncwarp();
    for (int d = lane; d < NDA; d += 32) {
        float acc = b1s[d];
        #pragma unroll 16
        for (int i = 0; i < NI; i++) acc = fmaf(xr[w][i], W1s[d][i], acc);
        ssm[w][d] = tanhf(acc);
    }
    __syncwarp();
    if (lane < NR) {
        float acc = b2s[lane];
        #pragma unroll
        for (int d = 0; d < NDA; d++) acc = fmaf(ssm[w][d], W2s[lane][d], acc);
        int b = bt >> 9, t = bt & 511;
        g_S[((size_t)b * NR + lane) * NT + t] = acc;
    }
}

// --------------- K2: max over t, exp, prefix-sum denominators ---------------
__global__ void k_maxexpdinv() {
    int br = blockIdx.x;
    int b = br / NR, r = br % NR;
    int tid = threadIdx.x;
    int w = tid >> 5, lane = tid & 31;
    const float* Sp = g_S + (size_t)br * NT;
    float4 v = *(const float4*)(Sp + 4 * tid);

    __shared__ float red[4];
    __shared__ float wsum[4];
    float m = fmaxf(fmaxf(v.x, v.y), fmaxf(v.z, v.w));
    for (int o = 16; o; o >>= 1) m = fmaxf(m, __shfl_xor_sync(~0u, m, o));
    if (lane == 0) red[w] = m;
    __syncthreads();
    m = fmaxf(fmaxf(red[0], red[1]), fmaxf(red[2], red[3]));

    float e0 = __expf(v.x - m), e1 = __expf(v.y - m);
    float e2 = __expf(v.z - m), e3 = __expf(v.w - m);
    float ls = e0 + e1 + e2 + e3;

    float s = ls;
    for (int o = 1; o < 32; o <<= 1) {
        float n = __shfl_up_sync(~0u, s, o);
        if (lane >= o) s += n;
    }
    if (lane == 31) wsum[w] = s;
    __syncthreads();
    float base = 0.0f;
    #pragma unroll
    for (int ww = 0; ww < 4; ww++) if (ww < w) base += wsum[ww];

    float excl = base + s - ls;
    float d0 = excl + e0;
    float d1 = d0 + e1;
    float d2 = d1 + e2;
    float d3 = d2 + e3;

    int t0 = 4 * tid;
    size_t a0 = ((size_t)b * NT + t0) * NR + r;
    g_E[a0]            = e0;
    g_E[a0 + NR]       = e1;
    g_E[a0 + 2 * NR]   = e2;
    g_E[a0 + 3 * NR]   = e3;
    g_Dinv[a0]          = __fdividef(1.0f, d0);
    g_Dinv[a0 + NR]     = __fdividef(1.0f, d1);
    g_Dinv[a0 + 2 * NR] = __fdividef(1.0f, d2);
    g_Dinv[a0 + 3 * NR] = __fdividef(1.0f, d3);
}

// --------------------- K3: M via per-chunk recompute ------------------------
__global__ void k_attnM(const float* __restrict__ x) {
    int bc = blockIdx.x;
    int b = bc >> 3, c = bc & 7;
    int i = threadIdx.x;
    float N[NR];
    #pragma unroll
    for (int r = 0; r < NR; r++) N[r] = 0.0f;

    const float* xb = x + ((size_t)b * NT) * NI + i;
    const float* Eb = g_E + ((size_t)b * NT) * NR;
    const float* Db = g_Dinv + ((size_t)b * NT) * NR;
    float* Mb = g_M + ((size_t)b * NT) * NI + i;

    int tstart = c * 64;
    for (int t = 0; t < tstart; t++) {
        float xv = xb[(size_t)t * NI];
        #pragma unroll
        for (int r = 0; r < NR; r++)
            N[r] = fmaf(Eb[(size_t)t * NR + r], xv, N[r]);
    }
    for (int tl = 0; tl < 64; tl++) {
        int t = tstart + tl;
        float xv = xb[(size_t)t * NI];
        float acc = 0.0f;
        #pragma unroll
        for (int r = 0; r < NR; r++) {
            N[r] = fmaf(Eb[(size_t)t * NR + r], xv, N[r]);
            acc = fmaf(N[r], Db[(size_t)t * NR + r], acc);
        }
        Mb[(size_t)t * NI] = acc * 0.05f;
    }
}

// --------------- K4: gx GEMM (f32x2, LDS-economical) ------------------------
// C[32768,1024] = M[32768,128] @ Wih[128,1024]. Tile 64m x 128n, K-chunks of 32.
// Thread tile 4m x 8n: per kk = 4 LDS.128 + 16 FFMA2 (32 MAC).
__global__ void __launch_bounds__(256) k_gemm(const float* __restrict__ Wih,
                                              const float* __restrict__ bias) {
    __shared__ float As2[32 * 132];    // [k][2m dup], stride 132 (16B aligned)
    __shared__ float Bs [32 * 128];    // [k][n]
    int tid = threadIdx.x;
    int tn = tid & 15, tm = tid >> 4;
    int m0 = blockIdx.x * 64;
    int n0 = blockIdx.y * 128;

    unsigned long long acc[4][4] = {};
    for (int kc = 0; kc < 4; kc++) {
        // A: 64 rows x 32 k  (coalesced along k)
        #pragma unroll
        for (int pass = 0; pass < 2; pass++) {
            int idx = tid + pass * 256;        // < 512
            int row = idx >> 3, c4 = idx & 7;
            float4 va = *(const float4*)&g_M[(size_t)(m0 + row) * NI + kc * 32 + c4 * 4];
            *(float2*)&As2[(c4 * 4 + 0) * 132 + 2 * row] = make_float2(va.x, va.x);
            *(float2*)&As2[(c4 * 4 + 1) * 132 + 2 * row] = make_float2(va.y, va.y);
            *(float2*)&As2[(c4 * 4 + 2) * 132 + 2 * row] = make_float2(va.z, va.z);
            *(float2*)&As2[(c4 * 4 + 3) * 132 + 2 * row] = make_float2(va.w, va.w);
        }
        // B: 32 k x 128 n
        #pragma unroll
        for (int pass = 0; pass < 4; pass++) {
            int idx = tid + pass * 256;        // < 1024
            int row = idx >> 5, c4 = idx & 31;
            float4 vb = *(const float4*)&Wih[(size_t)(kc * 32 + row) * G4 + n0 + c4 * 4];
            *(float4*)&Bs[row * 128 + c4 * 4] = vb;
        }
        __syncthreads();
        #pragma unroll 8
        for (int kk = 0; kk < 32; kk++) {
            ulonglong2 b01 = *(const ulonglong2*)&Bs[kk * 128 + tn * 8];
            ulonglong2 b23 = *(const ulonglong2*)&Bs[kk * 128 + tn * 8 + 4];
            ulonglong2 a01 = *(const ulonglong2*)&As2[kk * 132 + 8 * tm];
            ulonglong2 a23 = *(const ulonglong2*)&As2[kk * 132 + 8 * tm + 4];
            unsigned long long am[4] = {a01.x, a01.y, a23.x, a23.y};
            #pragma unroll
            for (int j = 0; j < 4; j++) {
                ffma2(acc[j][0], am[j], b01.x);
                ffma2(acc[j][1], am[j], b01.y);
                ffma2(acc[j][2], am[j], b23.x);
                ffma2(acc[j][3], am[j], b23.y);
            }
        }
        __syncthreads();
    }
    float4 bb0 = *(const float4*)&bias[n0 + tn * 8];
    float4 bb1 = *(const float4*)&bias[n0 + tn * 8 + 4];
    #pragma unroll
    for (int j = 0; j < 4; j++) {
        int m = m0 + tm * 4 + j;
        float2 p0 = *(float2*)&acc[j][0];
        float2 p1 = *(float2*)&acc[j][1];
        float2 p2 = *(float2*)&acc[j][2];
        float2 p3 = *(float2*)&acc[j][3];
        float4 o0 = make_float4(p0.x + bb0.x, p0.y + bb0.y, p1.x + bb0.z, p1.y + bb0.w);
        float4 o1 = make_float4(p2.x + bb1.x, p2.y + bb1.y, p3.x + bb1.z, p3.y + bb1.w);
        *(float4*)&g_GX[(size_t)m * G4 + n0 + tn * 8]     = o0;
        *(float4*)&g_GX[(size_t)m * G4 + n0 + tn * 8 + 4] = o1;
    }
}

// ---------------- K4b: repack GX [b*t][g] -> GXT [t][g][b] ------------------
__global__ void k_repack() {
    __shared__ float tile[32][33];
    int t = blockIdx.x;
    int c0 = blockIdx.y * 32;
    int b0 = blockIdx.z * 32;
    int tx = threadIdx.x & 31, ty = threadIdx.x >> 5;   // 32 x 8
    #pragma unroll
    for (int j = 0; j < 4; j++) {
        int row = ty + j * 8;
        tile[row][tx] = g_GX[((size_t)(b0 + row) * NT + t) * G4 + c0 + tx];
    }
    __syncthreads();
    #pragma unroll
    for (int j = 0; j < 4; j++) {
        int row = ty + j * 8;
        g_GXT[((size_t)t * G4 + c0 + row) * 64 + b0 + tx] = tile[tx][row];
    }
}

// ------------------------------ K5: LSTM recurrence -------------------------
#define LSTM_SMEM ((NH * 64 + NH * 16 + 4 * 8 * 64 + 128) * 4)

__global__ void __launch_bounds__(256, 1) k_lstm(const float* __restrict__ Whh) {
    extern __shared__ float sm[];
    float* hs   = sm;
    float* Ws2  = hs + NH * 64;
    float* gred = Ws2 + NH * 16;
    float* csm  = gred + 4 * 8 * 64;

    int bk = blockIdx.x;
    int tid = threadIdx.x;
    int p = tid & 15, q = (tid >> 4) & 3, u = tid >> 6;

    for (int idx = tid; idx < NH * 8; idx += 256) {
        int k = idx >> 3, c = idx & 7;
        float w = Whh[(size_t)k * G4 + (c & 3) * NH + 2 * bk + (c >> 2)];
        Ws2[idx * 2] = w;
        Ws2[idx * 2 + 1] = w;
    }
    if (tid < 128) csm[tid] = 1.0f;
    __syncthreads();

    int bbg = tid & 63, hig = (tid >> 6) & 1;

    float pg[4];
    if (tid < 128) {
        const float* gp = g_GXT + ((size_t)0 * G4 + 2 * bk + hig) * 64 + bbg;
        #pragma unroll
        for (int g = 0; g < 4; g++) pg[g] = __ldcs(gp + (size_t)g * NH * 64);
    }

    for (int t = 0; t < NT; t++) {
        const float* hin = g_h[t & 1];
        float* hout = g_h[(t + 1) & 1];

        float4 r1[8];
        #pragma unroll
        for (int j = 0; j < 8; j++)
            r1[j] = __ldcg((const float4*)(hin + tid * 4 + j * 1024));
        #pragma unroll
        for (int j = 0; j < 8; j++)
            *(float4*)(hs + tid * 4 + j * 1024) = r1[j];
        __syncthreads();

        float4 r2[8];
        #pragma unroll
        for (int j = 0; j < 8; j++)
            r2[j] = __ldcg((const float4*)(hin + 8192 + tid * 4 + j * 1024));

        unsigned long long a0 = 0ull, a1 = 0ull, a2 = 0ull, a3 = 0ull;
        {
            const float* hp = hs + (u * 32) * 64 + 4 * p;
            const float* wp = Ws2 + (u * 32) * 16 + 4 * q;
            #pragma unroll
            for (int k = 0; k < 32; k++) {
                ulonglong2 hv = *(const ulonglong2*)hp;
                ulonglong2 wv = *(const ulonglong2*)wp;
                ffma2(a0, hv.x, wv.x);
                ffma2(a1, hv.y, wv.x);
                ffma2(a2, hv.x, wv.y);
                ffma2(a3, hv.y, wv.y);
                hp += 64; wp += 16;
            }
        }
        #pragma unroll
        for (int j = 0; j < 8; j++)
            *(float4*)(hs + 8192 + tid * 4 + j * 1024) = r2[j];
        __syncthreads();
        {
            const float* hp = hs + (128 + u * 32) * 64 + 4 * p;
            const float* wp = Ws2 + (128 + u * 32) * 16 + 4 * q;
            #pragma unroll
            for (int k = 0; k < 32; k++) {
                ulonglong2 hv = *(const ulonglong2*)hp;
                ulonglong2 wv = *(const ulonglong2*)wp;
                ffma2(a0, hv.x, wv.x);
                ffma2(a1, hv.y, wv.x);
                ffma2(a2, hv.x, wv.y);
                ffma2(a3, hv.y, wv.y);
                hp += 64; wp += 16;
            }
        }
        {
            float* gr = gred + ((u * 8 + 2 * q) * 64 + 4 * p);
            ulonglong2 v01; v01.x = a0; v01.y = a1;
            ulonglong2 v23; v23.x = a2; v23.y = a3;
            *(ulonglong2*)gr = v01;
            *(ulonglong2*)(gr + 64) = v23;
        }
        __syncthreads();

        float pgn[4];
        if (tid < 128) {
            int tn = (t + 1) & (NT - 1);
            const float* gp = g_GXT + ((size_t)tn * G4 + 2 * bk + hig) * 64 + bbg;
            #pragma unroll
            for (int g = 0; g < 4; g++) pgn[g] = __ldcs(gp + (size_t)g * NH * 64);

            float gv[4];
            #pragma unroll
            for (int g = 0; g < 4; g++) {
                int c = hig * 4 + g;
                float s = gred[(0 * 8 + c) * 64 + bbg] + gred[(1 * 8 + c) * 64 + bbg]
                        + gred[(2 * 8 + c) * 64 + bbg] + gred[(3 * 8 + c) * 64 + bbg];
                gv[g] = s + pg[g];
            }
            float i_t = sigf(gv[0]);
            float f_t = sigf(gv[1]);
            float g_t = tanhfast(gv[2]);
            float o_t = sigf(gv[3]);
            float cc = f_t * csm[tid] + i_t * g_t;
            csm[tid] = cc;
            __stcg(&hout[(2 * bk + hig) * 64 + bbg], o_t * tanhfast(cc));
        }
        __syncthreads();

        if (tid == 0) {
            __threadfence();
            atomicAdd(&g_bar, 1u);
            unsigned target = 128u * (unsigned)(t + 1);
            while (*(volatile unsigned*)&g_bar < target) { }
        }
        __syncthreads();
        #pragma unroll
        for (int g = 0; g < 4; g++) pg[g] = pgn[g];
    }
}

// ------------------------------ K6: head + softmax --------------------------
__global__ void k_head(const float* __restrict__ Wfc, const float* __restrict__ bfc,
                       float* __restrict__ out) {
    int b = blockIdx.x;
    int lane = threadIdx.x;
    __shared__ float hsm[NH];
    for (int k = lane; k < NH; k += 32) hsm[k] = g_h[0][k * 64 + b];
    __syncwarp();
    float l = -1e30f;
    if (lane < NC) {
        float acc = bfc[lane];
        #pragma unroll 8
        for (int k = 0; k < NH; k++) acc = fmaf(hsm[k], Wfc[lane * NH + k], acc);
        l = acc;
    }
    float m = l;
    for (int o = 16; o; o >>= 1) m = fmaxf(m, __shfl_xor_sync(~0u, m, o));
    float e = (lane < NC) ? __expf(l - m) : 0.0f;
    float s = e;
    for (int o = 16; o; o >>= 1) s += __shfl_xor_sync(~0u, s, o);
    if (lane < NC) out[b * NC + lane] = e / s;
}

// ------------------------------ launch --------------------------------------
extern "C" void kernel_launch(void* const* d_in, const int* in_sizes, int n_in,
                              void* d_out, int out_size) {
    const float* x    = (const float*)d_in[0];
    const float* W_ih = (const float*)d_in[1];
    const float* W_hh = (const float*)d_in[2];
    const float* b    = (const float*)d_in[3];
    const float* W1   = (const float*)d_in[4];
    const float* b1   = (const float*)d_in[5];
    const float* W2   = (const float*)d_in[6];
    const float* b2   = (const float*)d_in[7];
    const float* Wfc  = (const float*)d_in[8];
    const float* bfc  = (const float*)d_in[9];
    float* out = (float*)d_out;

    cudaFuncSetAttribute(k_lstm, cudaFuncAttributeMaxDynamicSharedMemorySize, LSTM_SMEM);

    k_scores<<<4096, 256>>>(x, W1, b1, W2, b2);            // idx 0
    k_maxexpdinv<<<NB * NR, 128>>>();                      // idx 1
    k_attnM<<<NB * 8, 128>>>(x);                           // idx 2
    {
        dim3 grid(512, 8);
        k_gemm<<<grid, 256>>>(W_ih, b);                    // idx 3 (ncu target)
    }
    {
        dim3 grid(NT, 32, 2);
        k_repack<<<grid, 256>>>();                         // idx 4
    }
    k_lstm<<<128, 256, LSTM_SMEM>>>(W_hh);                 // idx 5
    k_head<<<NB, 32>>>(Wfc, bfc, out);                     // idx 6
}

// round 7
// speedup vs baseline: 1.1592x; 1.0384x over previous
#include <cuda_runtime.h>
#include <cuda_bf16.h>
#include <cstdint>

#define NB 64
#define NT 512
#define NI 128
#define NH 256
#define NR 20
#define NDA 50
#define NC 10
#define G4 1024

// ----------------------------- device scratch ------------------------------
__device__ float g_S   [NB * NR * NT];              // [b][r][t]
__device__ float g_E   [NB * NT * NR];              // [b][t][r]
__device__ float g_Dinv[NB * NT * NR];              // [b][t][r]
__device__ float g_MT  [(size_t)NT * NI * NB];      // [t][i][b]
__device__ float g_h   [2][NH * 64];                // [buf][hd*64 + b]
__device__ unsigned g_bar;

__device__ __forceinline__ void ffma2(unsigned long long& acc,
                                      unsigned long long a,
                                      unsigned long long b) {
    asm("fma.rn.f32x2 %0, %1, %2, %0;" : "+l"(acc) : "l"(a), "l"(b));
}
__device__ __forceinline__ float sigmoidf_(float v) {
    return 1.0f / (1.0f + __expf(-v));
}

// ------------------------------ K1: scores (+init) --------------------------
__global__ void k_scores(const float* __restrict__ x,
                         const float* __restrict__ W1, const float* __restrict__ b1,
                         const float* __restrict__ W2, const float* __restrict__ b2) {
    __shared__ float W1s[NDA][NI + 1];
    __shared__ float W2s[NR][NDA + 1];
    __shared__ float b1s[NDA];
    __shared__ float b2s[NR];
    __shared__ float xr[8][NI];
    __shared__ float ssm[8][NDA + 1];
    int tid = threadIdx.x;

    if (blockIdx.x == 0) {
        for (int j = tid; j < NH * 64; j += 256) g_h[0][j] = 1.0f;
        if (tid == 0) g_bar = 0u;
    }

    for (int idx = tid; idx < NDA * NI; idx += 256) W1s[idx / NI][idx % NI] = W1[idx];
    for (int idx = tid; idx < NR * NDA; idx += 256) W2s[idx / NDA][idx % NDA] = W2[idx];
    if (tid < NDA) b1s[tid] = b1[tid];
    if (tid < NR)  b2s[tid] = b2[tid];
    __syncthreads();

    int w = tid >> 5, lane = tid & 31;
    int bt = blockIdx.x * 8 + w;
    const float* xp = x + (size_t)bt * NI;
    for (int i = lane; i < NI; i += 32) xr[w][i] = xp[i];
    __syncwarp();
    for (int d = lane; d < NDA; d += 32) {
        float acc = b1s[d];
        #pragma unroll 16
        for (int i = 0; i < NI; i++) acc = fmaf(xr[w][i], W1s[d][i], acc);
        ssm[w][d] = tanhf(acc);
    }
    __syncwarp();
    if (lane < NR) {
        float acc = b2s[lane];
        #pragma unroll
        for (int d = 0; d < NDA; d++) acc = fmaf(ssm[w][d], W2s[lane][d], acc);
        int b = bt >> 9, t = bt & 511;
        g_S[((size_t)b * NR + lane) * NT + t] = acc;
    }
}

// --------------- K2: max over t, exp, prefix-sum denominators ---------------
__global__ void k_maxexpdinv() {
    int br = blockIdx.x;
    int b = br / NR, r = br % NR;
    int tid = threadIdx.x;
    int w = tid >> 5, lane = tid & 31;
    const float* Sp = g_S + (size_t)br * NT;
    float4 v = *(const float4*)(Sp + 4 * tid);

    __shared__ float red[4];
    __shared__ float wsum[4];
    float m = fmaxf(fmaxf(v.x, v.y), fmaxf(v.z, v.w));
    for (int o = 16; o; o >>= 1) m = fmaxf(m, __shfl_xor_sync(~0u, m, o));
    if (lane == 0) red[w] = m;
    __syncthreads();
    m = fmaxf(fmaxf(red[0], red[1]), fmaxf(red[2], red[3]));

    float e0 = __expf(v.x - m), e1 = __expf(v.y - m);
    float e2 = __expf(v.z - m), e3 = __expf(v.w - m);
    float ls = e0 + e1 + e2 + e3;

    float s = ls;
    for (int o = 1; o < 32; o <<= 1) {
        float n = __shfl_up_sync(~0u, s, o);
        if (lane >= o) s += n;
    }
    if (lane == 31) wsum[w] = s;
    __syncthreads();
    float base = 0.0f;
    #pragma unroll
    for (int ww = 0; ww < 4; ww++) if (ww < w) base += wsum[ww];

    float excl = base + s - ls;
    float d0 = excl + e0;
    float d1 = d0 + e1;
    float d2 = d1 + e2;
    float d3 = d2 + e3;

    int t0 = 4 * tid;
    size_t a0 = ((size_t)b * NT + t0) * NR + r;
    g_E[a0]            = e0;
    g_E[a0 + NR]       = e1;
    g_E[a0 + 2 * NR]   = e2;
    g_E[a0 + 3 * NR]   = e3;
    g_Dinv[a0]          = __fdividef(1.0f, d0);
    g_Dinv[a0 + NR]     = __fdividef(1.0f, d1);
    g_Dinv[a0 + 2 * NR] = __fdividef(1.0f, d2);
    g_Dinv[a0 + 3 * NR] = __fdividef(1.0f, d3);
}

// ------- K3: M via per-chunk recompute; writes MT[t][i][b] directly ---------
__global__ void k_attnM(const float* __restrict__ x) {
    int bc = blockIdx.x;
    int b = bc >> 3, c = bc & 7;
    int i = threadIdx.x;
    float N[NR];
    #pragma unroll
    for (int r = 0; r < NR; r++) N[r] = 0.0f;

    const float* xb = x + ((size_t)b * NT) * NI + i;
    const float* Eb = g_E + ((size_t)b * NT) * NR;
    const float* Db = g_Dinv + ((size_t)b * NT) * NR;

    int tstart = c * 64;
    for (int t = 0; t < tstart; t++) {
        float xv = xb[(size_t)t * NI];
        #pragma unroll
        for (int r = 0; r < NR; r++)
            N[r] = fmaf(Eb[(size_t)t * NR + r], xv, N[r]);
    }
    for (int tl = 0; tl < 64; tl++) {
        int t = tstart + tl;
        float xv = xb[(size_t)t * NI];
        float acc = 0.0f;
        #pragma unroll
        for (int r = 0; r < NR; r++) {
            N[r] = fmaf(Eb[(size_t)t * NR + r], xv, N[r]);
            acc = fmaf(N[r], Db[(size_t)t * NR + r], acc);
        }
        g_MT[((size_t)t * NI + i) * 64 + b] = acc * 0.05f;
    }
}

// ---------------- K4: fused LSTM (recurrent dot + gx dot) -------------------
// 128 persistent blocks x 256 threads. Block bk owns h-dims {2bk,2bk+1} -> 8 gate cols.
// Thread (p = tid&15 : 4 batches, q = (tid>>4)&3 : 2 cols, u = tid>>6 : k-quarter).
// smem floats: hs 16384 | Ws2 4096 | Wis2 2048 | Ms 8192 | gred 2048 | csm 128 | bs 8
#define LSTM_SMEM ((16384 + 4096 + 2048 + 8192 + 2048 + 128 + 8) * 4)

__global__ void __launch_bounds__(256, 1) k_lstm(const float* __restrict__ Whh,
                                                 const float* __restrict__ Wih,
                                                 const float* __restrict__ bias) {
    extern __shared__ float sm[];
    float* hs   = sm;                  // h staged [k=256][b=64]
    float* Ws2  = hs + 16384;          // Whh slice, pair-dup [k=256][16]
    float* Wis2 = Ws2 + 4096;          // Wih slice, pair-dup [i=128][16]
    float* Ms   = Wis2 + 2048;         // M_t staged [i=128][b=64]
    float* gred = Ms + 8192;           // [u=4][c=8][b=64]
    float* csm  = gred + 2048;         // c state, 128
    float* bs   = csm + 128;           // bias, 8

    int bk = blockIdx.x;
    int tid = threadIdx.x;
    int p = tid & 15, q = (tid >> 4) & 3, u = tid >> 6;

    for (int idx = tid; idx < NH * 8; idx += 256) {      // Whh slice
        int k = idx >> 3, c = idx & 7;
        float w = Whh[(size_t)k * G4 + (c & 3) * NH + 2 * bk + (c >> 2)];
        Ws2[idx * 2] = w;
        Ws2[idx * 2 + 1] = w;
    }
    for (int idx = tid; idx < NI * 8; idx += 256) {      // Wih slice
        int k = idx >> 3, c = idx & 7;
        float w = Wih[(size_t)k * G4 + (c & 3) * NH + 2 * bk + (c >> 2)];
        Wis2[idx * 2] = w;
        Wis2[idx * 2 + 1] = w;
    }
    if (tid < 8) bs[tid] = bias[(tid & 3) * NH + 2 * bk + (tid >> 2)];
    if (tid < 128) csm[tid] = 1.0f;
    __syncthreads();

    int bbg = tid & 63, hig = (tid >> 6) & 1;

    for (int t = 0; t < NT; t++) {
        const float* hin = g_h[t & 1];
        float* hout = g_h[(t + 1) & 1];
        const float* mt = g_MT + (size_t)t * (NI * 64);

        // issue h half1 + M_t loads
        float4 r1[8], rm[8];
        #pragma unroll
        for (int j = 0; j < 8; j++)
            r1[j] = __ldcg((const float4*)(hin + tid * 4 + j * 1024));
        #pragma unroll
        for (int j = 0; j < 8; j++)
            rm[j] = __ldcg((const float4*)(mt + tid * 4 + j * 1024));
        #pragma unroll
        for (int j = 0; j < 8; j++)
            *(float4*)(Ms + tid * 4 + j * 1024) = rm[j];
        __syncthreads();                                  // (1) Ms ready

        #pragma unroll
        for (int j = 0; j < 8; j++)
            *(float4*)(hs + tid * 4 + j * 1024) = r1[j];
        float4 r2[8];
        #pragma unroll
        for (int j = 0; j < 8; j++)
            r2[j] = __ldcg((const float4*)(hin + 8192 + tid * 4 + j * 1024));

        unsigned long long a0 = 0ull, a1 = 0ull, a2 = 0ull, a3 = 0ull;
        {   // gx dot (independent of h): k in [u*32, u*32+32) over M
            const float* mp = Ms + (u * 32) * 64 + 4 * p;
            const float* wp = Wis2 + (u * 32) * 16 + 4 * q;
            #pragma unroll
            for (int k = 0; k < 32; k++) {
                ulonglong2 hv = *(const ulonglong2*)mp;
                ulonglong2 wv = *(const ulonglong2*)wp;
                ffma2(a0, hv.x, wv.x);
                ffma2(a1, hv.y, wv.x);
                ffma2(a2, hv.x, wv.y);
                ffma2(a3, hv.y, wv.y);
                mp += 64; wp += 16;
            }
        }
        __syncthreads();                                  // (2) hs half1 ready
        {   // recurrent phase A: k in [u*32, u*32+32)
            const float* hp = hs + (u * 32) * 64 + 4 * p;
            const float* wp = Ws2 + (u * 32) * 16 + 4 * q;
            #pragma unroll
            for (int k = 0; k < 32; k++) {
                ulonglong2 hv = *(const ulonglong2*)hp;
                ulonglong2 wv = *(const ulonglong2*)wp;
                ffma2(a0, hv.x, wv.x);
                ffma2(a1, hv.y, wv.x);
                ffma2(a2, hv.x, wv.y);
                ffma2(a3, hv.y, wv.y);
                hp += 64; wp += 16;
            }
        }
        #pragma unroll
        for (int j = 0; j < 8; j++)
            *(float4*)(hs + 8192 + tid * 4 + j * 1024) = r2[j];
        __syncthreads();                                  // (3) hs half2 ready
        {   // recurrent phase B: k in [128 + u*32, ...)
            const float* hp = hs + (128 + u * 32) * 64 + 4 * p;
            const float* wp = Ws2 + (128 + u * 32) * 16 + 4 * q;
            #pragma unroll
            for (int k = 0; k < 32; k++) {
                ulonglong2 hv = *(const ulonglong2*)hp;
                ulonglong2 wv = *(const ulonglong2*)wp;
                ffma2(a0, hv.x, wv.x);
                ffma2(a1, hv.y, wv.x);
                ffma2(a2, hv.x, wv.y);
                ffma2(a3, hv.y, wv.y);
                hp += 64; wp += 16;
            }
        }
        {
            float* gr = gred + ((u * 8 + 2 * q) * 64 + 4 * p);
            ulonglong2 v01; v01.x = a0; v01.y = a1;
            ulonglong2 v23; v23.x = a2; v23.y = a3;
            *(ulonglong2*)gr = v01;
            *(ulonglong2*)(gr + 64) = v23;
        }
        __syncthreads();                                  // (4) gred ready

        if (tid < 128) {
            float gv[4];
            #pragma unroll
            for (int g = 0; g < 4; g++) {
                int c = hig * 4 + g;
                float s = gred[(0 * 8 + c) * 64 + bbg] + gred[(1 * 8 + c) * 64 + bbg]
                        + gred[(2 * 8 + c) * 64 + bbg] + gred[(3 * 8 + c) * 64 + bbg];
                gv[g] = s + bs[c];
            }
            float i_t = sigmoidf_(gv[0]);
            float f_t = sigmoidf_(gv[1]);
            float g_t = tanhf(gv[2]);
            float o_t = sigmoidf_(gv[3]);
            float cc = f_t * csm[tid] + i_t * g_t;
            csm[tid] = cc;
            __stcg(&hout[(2 * bk + hig) * 64 + bbg], o_t * tanhf(cc));
        }
        __syncthreads();                                  // (5) all h written

        if (tid == 0) {
            __threadfence();
            atomicAdd(&g_bar, 1u);
            unsigned target = 128u * (unsigned)(t + 1);
            while (*(volatile unsigned*)&g_bar < target) { }
        }
        __syncthreads();                                  // (6) barrier release
    }
}

// ------------------------------ K5: head + softmax --------------------------
__global__ void k_head(const float* __restrict__ Wfc, const float* __restrict__ bfc,
                       float* __restrict__ out) {
    int b = blockIdx.x;
    int lane = threadIdx.x;
    __shared__ float hsm[NH];
    for (int k = lane; k < NH; k += 32) hsm[k] = g_h[0][k * 64 + b];
    __syncwarp();
    float l = -1e30f;
    if (lane < NC) {
        float acc = bfc[lane];
        #pragma unroll 8
        for (int k = 0; k < NH; k++) acc = fmaf(hsm[k], Wfc[lane * NH + k], acc);
        l = acc;
    }
    float m = l;
    for (int o = 16; o; o >>= 1) m = fmaxf(m, __shfl_xor_sync(~0u, m, o));
    float e = (lane < NC) ? __expf(l - m) : 0.0f;
    float s = e;
    for (int o = 16; o; o >>= 1) s += __shfl_xor_sync(~0u, s, o);
    if (lane < NC) out[b * NC + lane] = e / s;
}

// ------------------------------ launch --------------------------------------
extern "C" void kernel_launch(void* const* d_in, const int* in_sizes, int n_in,
                              void* d_out, int out_size) {
    const float* x    = (const float*)d_in[0];
    const float* W_ih = (const float*)d_in[1];
    const float* W_hh = (const float*)d_in[2];
    const float* b    = (const float*)d_in[3];
    const float* W1   = (const float*)d_in[4];
    const float* b1   = (const float*)d_in[5];
    const float* W2   = (const float*)d_in[6];
    const float* b2   = (const float*)d_in[7];
    const float* Wfc  = (const float*)d_in[8];
    const float* bfc  = (const float*)d_in[9];
    float* out = (float*)d_out;

    cudaFuncSetAttribute(k_lstm, cudaFuncAttributeMaxDynamicSharedMemorySize, LSTM_SMEM);

    k_scores<<<4096, 256>>>(x, W1, b1, W2, b2);            // idx 0
    k_maxexpdinv<<<NB * NR, 128>>>();                      // idx 1
    k_attnM<<<NB * 8, 128>>>(x);                           // idx 2
    k_lstm<<<128, 256, LSTM_SMEM>>>(W_hh, W_ih, b);        // idx 3 (ncu slot)
    k_head<<<NB, 32>>>(Wfc, bfc, out);                     // idx 4
}

// round 8
// speedup vs baseline: 1.3070x; 1.1275x over previous
#include <cuda_runtime.h>
#include <cuda_bf16.h>
#include <cstdint>

#define NB 64
#define NT 512
#define NI 128
#define NH 256
#define NR 20
#define NDA 50
#define NC 10
#define G4 1024

// ----------------------------- device scratch ------------------------------
__device__ float g_S   [NB * NR * NT];              // [b][r][t]
__device__ float g_E   [NB * NT * NR];              // [b][t][r]
__device__ float g_Dinv[NB * NT * NR];              // [b][t][r]
__device__ float g_MT  [(size_t)NT * NI * NB];      // [t][i][b]
__device__ float g_h   [2][NH * 64];                // [buf][hd*64 + b]
__device__ unsigned g_flags[128];                   // per-block step flags

__device__ __forceinline__ void ffma2(unsigned long long& acc,
                                      unsigned long long a,
                                      unsigned long long b) {
    asm("fma.rn.f32x2 %0, %1, %2, %0;" : "+l"(acc) : "l"(a), "l"(b));
}
__device__ __forceinline__ float sigmoidf_(float v) {
    return 1.0f / (1.0f + __expf(-v));
}

// ------------------------------ K1: scores (+init) --------------------------
__global__ void k_scores(const float* __restrict__ x,
                         const float* __restrict__ W1, const float* __restrict__ b1,
                         const float* __restrict__ W2, const float* __restrict__ b2) {
    __shared__ float W1s[NDA][NI + 1];
    __shared__ float W2s[NR][NDA + 1];
    __shared__ float b1s[NDA];
    __shared__ float b2s[NR];
    __shared__ float xr[8][NI];
    __shared__ float ssm[8][NDA + 1];
    int tid = threadIdx.x;

    if (blockIdx.x == 0) {
        for (int j = tid; j < NH * 64; j += 256) g_h[0][j] = 1.0f;
        if (tid < 128) g_flags[tid] = 0u;
    }

    for (int idx = tid; idx < NDA * NI; idx += 256) W1s[idx / NI][idx % NI] = W1[idx];
    for (int idx = tid; idx < NR * NDA; idx += 256) W2s[idx / NDA][idx % NDA] = W2[idx];
    if (tid < NDA) b1s[tid] = b1[tid];
    if (tid < NR)  b2s[tid] = b2[tid];
    __syncthreads();

    int w = tid >> 5, lane = tid & 31;
    int bt = blockIdx.x * 8 + w;
    const float* xp = x + (size_t)bt * NI;
    for (int i = lane; i < NI; i += 32) xr[w][i] = xp[i];
    __syncwarp();
    for (int d = lane; d < NDA; d += 32) {
        float acc = b1s[d];
        #pragma unroll 16
        for (int i = 0; i < NI; i++) acc = fmaf(xr[w][i], W1s[d][i], acc);
        ssm[w][d] = tanhf(acc);
    }
    __syncwarp();
    if (lane < NR) {
        float acc = b2s[lane];
        #pragma unroll
        for (int d = 0; d < NDA; d++) acc = fmaf(ssm[w][d], W2s[lane][d], acc);
        int b = bt >> 9, t = bt & 511;
        g_S[((size_t)b * NR + lane) * NT + t] = acc;
    }
}

// --------------- K2: max over t, exp, prefix-sum denominators ---------------
__global__ void k_maxexpdinv() {
    int br = blockIdx.x;
    int b = br / NR, r = br % NR;
    int tid = threadIdx.x;
    int w = tid >> 5, lane = tid & 31;
    const float* Sp = g_S + (size_t)br * NT;
    float4 v = *(const float4*)(Sp + 4 * tid);

    __shared__ float red[4];
    __shared__ float wsum[4];
    float m = fmaxf(fmaxf(v.x, v.y), fmaxf(v.z, v.w));
    for (int o = 16; o; o >>= 1) m = fmaxf(m, __shfl_xor_sync(~0u, m, o));
    if (lane == 0) red[w] = m;
    __syncthreads();
    m = fmaxf(fmaxf(red[0], red[1]), fmaxf(red[2], red[3]));

    float e0 = __expf(v.x - m), e1 = __expf(v.y - m);
    float e2 = __expf(v.z - m), e3 = __expf(v.w - m);
    float ls = e0 + e1 + e2 + e3;

    float s = ls;
    for (int o = 1; o < 32; o <<= 1) {
        float n = __shfl_up_sync(~0u, s, o);
        if (lane >= o) s += n;
    }
    if (lane == 31) wsum[w] = s;
    __syncthreads();
    float base = 0.0f;
    #pragma unroll
    for (int ww = 0; ww < 4; ww++) if (ww < w) base += wsum[ww];

    float excl = base + s - ls;
    float d0 = excl + e0;
    float d1 = d0 + e1;
    float d2 = d1 + e2;
    float d3 = d2 + e3;

    int t0 = 4 * tid;
    size_t a0 = ((size_t)b * NT + t0) * NR + r;
    g_E[a0]            = e0;
    g_E[a0 + NR]       = e1;
    g_E[a0 + 2 * NR]   = e2;
    g_E[a0 + 3 * NR]   = e3;
    g_Dinv[a0]          = __fdividef(1.0f, d0);
    g_Dinv[a0 + NR]     = __fdividef(1.0f, d1);
    g_Dinv[a0 + 2 * NR] = __fdividef(1.0f, d2);
    g_Dinv[a0 + 3 * NR] = __fdividef(1.0f, d3);
}

// ------- K3: M via per-chunk recompute; writes MT[t][i][b] directly ---------
__global__ void k_attnM(const float* __restrict__ x) {
    int bc = blockIdx.x;
    int b = bc >> 3, c = bc & 7;
    int i = threadIdx.x;
    float N[NR];
    #pragma unroll
    for (int r = 0; r < NR; r++) N[r] = 0.0f;

    const float* xb = x + ((size_t)b * NT) * NI + i;
    const float* Eb = g_E + ((size_t)b * NT) * NR;
    const float* Db = g_Dinv + ((size_t)b * NT) * NR;

    int tstart = c * 64;
    for (int t = 0; t < tstart; t++) {
        float xv = xb[(size_t)t * NI];
        #pragma unroll
        for (int r = 0; r < NR; r++)
            N[r] = fmaf(Eb[(size_t)t * NR + r], xv, N[r]);
    }
    for (int tl = 0; tl < 64; tl++) {
        int t = tstart + tl;
        float xv = xb[(size_t)t * NI];
        float acc = 0.0f;
        #pragma unroll
        for (int r = 0; r < NR; r++) {
            N[r] = fmaf(Eb[(size_t)t * NR + r], xv, N[r]);
            acc = fmaf(N[r], Db[(size_t)t * NR + r], acc);
        }
        g_MT[((size_t)t * NI + i) * 64 + b] = acc * 0.05f;
    }
}

// ---------------- K4: fused LSTM, gx computed in barrier window -------------
// 128 persistent blocks x 256 threads. Block bk owns h-dims {2bk,2bk+1} -> 8 cols.
// Thread (p=tid&15: 4 batches, q=(tid>>4)&3: 2 cols, u=tid>>6: k-quarter).
// smem floats: hs 16384 | Ws2 4096 | Wis2 2048 | Ms 2*8192 | gred 2048 | csm 128 | bs 8
#define LSTM_SMEM ((16384 + 4096 + 2048 + 16384 + 2048 + 128 + 8) * 4)

__global__ void __launch_bounds__(256, 1) k_lstm(const float* __restrict__ Whh,
                                                 const float* __restrict__ Wih,
                                                 const float* __restrict__ bias) {
    extern __shared__ float sm[];
    float* hs   = sm;                  // [k=256][b=64]
    float* Ws2  = hs + 16384;          // Whh slice pair-dup [k=256][16]
    float* Wis2 = Ws2 + 4096;          // Wih slice pair-dup [i=128][16]
    float* Ms   = Wis2 + 2048;         // M double buffer [2][i=128][b=64]
    float* gred = Ms + 16384;          // [u=4][c=8][b=64]
    float* csm  = gred + 2048;         // c state
    float* bs   = csm + 128;           // bias slice

    int bk = blockIdx.x;
    int tid = threadIdx.x;
    int p = tid & 15, q = (tid >> 4) & 3, u = tid >> 6;

    for (int idx = tid; idx < NH * 8; idx += 256) {
        int k = idx >> 3, c = idx & 7;
        float w = Whh[(size_t)k * G4 + (c & 3) * NH + 2 * bk + (c >> 2)];
        Ws2[idx * 2] = w;
        Ws2[idx * 2 + 1] = w;
    }
    for (int idx = tid; idx < NI * 8; idx += 256) {
        int k = idx >> 3, c = idx & 7;
        float w = Wih[(size_t)k * G4 + (c & 3) * NH + 2 * bk + (c >> 2)];
        Wis2[idx * 2] = w;
        Wis2[idx * 2 + 1] = w;
    }
    if (tid < 8) bs[tid] = bias[(tid & 3) * NH + 2 * bk + (tid >> 2)];
    if (tid < 128) csm[tid] = 1.0f;

    // ---- prologue: stage M_0, compute gx partials for t=0 ----
    {
        float4 rm0[8];
        #pragma unroll
        for (int j = 0; j < 8; j++)
            rm0[j] = __ldcg((const float4*)(g_MT + tid * 4 + j * 1024));
        #pragma unroll
        for (int j = 0; j < 8; j++)
            *(float4*)(Ms + tid * 4 + j * 1024) = rm0[j];
    }
    __syncthreads();
    unsigned long long gx0 = 0ull, gx1 = 0ull, gx2 = 0ull, gx3 = 0ull;
    {
        const float* mp = Ms + (u * 32) * 64 + 4 * p;
        const float* wp = Wis2 + (u * 32) * 16 + 4 * q;
        #pragma unroll
        for (int k = 0; k < 32; k++) {
            ulonglong2 mv = *(const ulonglong2*)mp;
            ulonglong2 wv = *(const ulonglong2*)wp;
            ffma2(gx0, mv.x, wv.x);
            ffma2(gx1, mv.y, wv.x);
            ffma2(gx2, mv.x, wv.y);
            ffma2(gx3, mv.y, wv.y);
            mp += 64; wp += 16;
        }
    }

    int bbg = tid & 63, hig = (tid >> 6) & 1;

    for (int t = 0; t < NT; t++) {
        const float* hin = g_h[t & 1];
        float* hout = g_h[(t + 1) & 1];
        const float* mnext = g_MT + (size_t)((t + 1) & (NT - 1)) * (NI * 64);
        float* msbuf = Ms + ((t + 1) & 1) * 8192;

        // issue M_{t+1} + h half1 loads
        float4 rm[8], r1[8];
        #pragma unroll
        for (int j = 0; j < 8; j++)
            rm[j] = __ldcg((const float4*)(mnext + tid * 4 + j * 1024));
        #pragma unroll
        for (int j = 0; j < 8; j++)
            r1[j] = __ldcg((const float4*)(hin + tid * 4 + j * 1024));
        #pragma unroll
        for (int j = 0; j < 8; j++)
            *(float4*)(hs + tid * 4 + j * 1024) = r1[j];
        __syncthreads();                                   // (1) hs half1 ready

        float4 r2[8];
        #pragma unroll
        for (int j = 0; j < 8; j++)
            r2[j] = __ldcg((const float4*)(hin + 8192 + tid * 4 + j * 1024));

        unsigned long long a0 = gx0, a1 = gx1, a2 = gx2, a3 = gx3;
        {   // recurrent phase A: k in [u*32, u*32+32)
            const float* hp = hs + (u * 32) * 64 + 4 * p;
            const float* wp = Ws2 + (u * 32) * 16 + 4 * q;
            #pragma unroll
            for (int k = 0; k < 32; k++) {
                ulonglong2 hv = *(const ulonglong2*)hp;
                ulonglong2 wv = *(const ulonglong2*)wp;
                ffma2(a0, hv.x, wv.x);
                ffma2(a1, hv.y, wv.x);
                ffma2(a2, hv.x, wv.y);
                ffma2(a3, hv.y, wv.y);
                hp += 64; wp += 16;
            }
        }
        #pragma unroll
        for (int j = 0; j < 8; j++)
            *(float4*)(hs + 8192 + tid * 4 + j * 1024) = r2[j];
        __syncthreads();                                   // (2) hs half2 ready
        {   // recurrent phase B
            const float* hp = hs + (128 + u * 32) * 64 + 4 * p;
            const float* wp = Ws2 + (128 + u * 32) * 16 + 4 * q;
            #pragma unroll
            for (int k = 0; k < 32; k++) {
                ulonglong2 hv = *(const ulonglong2*)hp;
                ulonglong2 wv = *(const ulonglong2*)wp;
                ffma2(a0, hv.x, wv.x);
                ffma2(a1, hv.y, wv.x);
                ffma2(a2, hv.x, wv.y);
                ffma2(a3, hv.y, wv.y);
                hp += 64; wp += 16;
            }
        }
        {
            float* gr = gred + ((u * 8 + 2 * q) * 64 + 4 * p);
            ulonglong2 v01; v01.x = a0; v01.y = a1;
            ulonglong2 v23; v23.x = a2; v23.y = a3;
            *(ulonglong2*)gr = v01;
            *(ulonglong2*)(gr + 64) = v23;
        }
        // park M_{t+1} into its smem buffer (read only after sync(3))
        #pragma unroll
        for (int j = 0; j < 8; j++)
            *(float4*)(msbuf + tid * 4 + j * 1024) = rm[j];
        __syncthreads();                                   // (3) gred + Ms ready

        if (tid < 128) {
            float gv[4];
            #pragma unroll
            for (int g = 0; g < 4; g++) {
                int c = hig * 4 + g;
                float s = gred[(0 * 8 + c) * 64 + bbg] + gred[(1 * 8 + c) * 64 + bbg]
                        + gred[(2 * 8 + c) * 64 + bbg] + gred[(3 * 8 + c) * 64 + bbg];
                gv[g] = s + bs[c];
            }
            float i_t = sigmoidf_(gv[0]);
            float f_t = sigmoidf_(gv[1]);
            float g_t = tanhf(gv[2]);
            float o_t = sigmoidf_(gv[3]);
            float cc = f_t * csm[tid] + i_t * g_t;
            csm[tid] = cc;
            __stcg(&hout[(2 * bk + hig) * 64 + bbg], o_t * tanhf(cc));
        }
        __syncthreads();                                   // (4) all h written

        // arrive: release flag (orders the block's h stores)
        if (tid == 0) {
            asm volatile("st.release.gpu.global.u32 [%0], %1;"
                         :: "l"(&g_flags[bk]), "r"((unsigned)(t + 1)) : "memory");
        }

        // compute gx partials for t+1 while other blocks finish
        gx0 = 0ull; gx1 = 0ull; gx2 = 0ull; gx3 = 0ull;
        {
            const float* mp = msbuf + (u * 32) * 64 + 4 * p;
            const float* wp = Wis2 + (u * 32) * 16 + 4 * q;
            #pragma unroll
            for (int k = 0; k < 32; k++) {
                ulonglong2 mv = *(const ulonglong2*)mp;
                ulonglong2 wv = *(const ulonglong2*)wp;
                ffma2(gx0, mv.x, wv.x);
                ffma2(gx1, mv.y, wv.x);
                ffma2(gx2, mv.x, wv.y);
                ffma2(gx3, mv.y, wv.y);
                mp += 64; wp += 16;
            }
        }

        // wait: 128 parallel pollers, one flag each
        if (tid < 128) {
            unsigned v;
            do {
                asm volatile("ld.acquire.gpu.global.u32 %0, [%1];"
                             : "=r"(v) : "l"(&g_flags[tid]));
            } while (v < (unsigned)(t + 1));
        }
        __syncthreads();                                   // (5) barrier release
    }
}

// ------------------------------ K5: head + softmax --------------------------
__global__ void k_head(const float* __restrict__ Wfc, const float* __restrict__ bfc,
                       float* __restrict__ out) {
    int b = blockIdx.x;
    int lane = threadIdx.x;
    __shared__ float hsm[NH];
    for (int k = lane; k < NH; k += 32) hsm[k] = g_h[0][k * 64 + b];
    __syncwarp();
    float l = -1e30f;
    if (lane < NC) {
        float acc = bfc[lane];
        #pragma unroll 8
        for (int k = 0; k < NH; k++) acc = fmaf(hsm[k], Wfc[lane * NH + k], acc);
        l = acc;
    }
    float m = l;
    for (int o = 16; o; o >>= 1) m = fmaxf(m, __shfl_xor_sync(~0u, m, o));
    float e = (lane < NC) ? __expf(l - m) : 0.0f;
    float s = e;
    for (int o = 16; o; o >>= 1) s += __shfl_xor_sync(~0u, s, o);
    if (lane < NC) out[b * NC + lane] = e / s;
}

// ------------------------------ launch --------------------------------------
extern "C" void kernel_launch(void* const* d_in, const int* in_sizes, int n_in,
                              void* d_out, int out_size) {
    const float* x    = (const float*)d_in[0];
    const float* W_ih = (const float*)d_in[1];
    const float* W_hh = (const float*)d_in[2];
    const float* b    = (const float*)d_in[3];
    const float* W1   = (const float*)d_in[4];
    const float* b1   = (const float*)d_in[5];
    const float* W2   = (const float*)d_in[6];
    const float* b2   = (const float*)d_in[7];
    const float* Wfc  = (const float*)d_in[8];
    const float* bfc  = (const float*)d_in[9];
    float* out = (float*)d_out;

    cudaFuncSetAttribute(k_lstm, cudaFuncAttributeMaxDynamicSharedMemorySize, LSTM_SMEM);

    k_scores<<<4096, 256>>>(x, W1, b1, W2, b2);            // idx 0
    k_maxexpdinv<<<NB * NR, 128>>>();                      // idx 1
    k_attnM<<<NB * 8, 128>>>(x);                           // idx 2
    k_lstm<<<128, 256, LSTM_SMEM>>>(W_hh, W_ih, b);        // idx 3 (ncu slot)
    k_head<<<NB, 32>>>(Wfc, bfc, out);                     // idx 4
}